// round 8
// baseline (speedup 1.0000x reference)
#include <cuda_runtime.h>

#define NN 50000
#define NE 1600000
#define NB_NODE 196              // ceil(NN/256)

typedef unsigned long long ull;

struct __align__(8) EP { int s; float w; };

// ---------------- scratch (device globals; no allocations) ----------------
__device__ float g_degW[NN];
__device__ float g_dinv[NN];
__device__ int   g_cnt[NN];
__device__ int   g_bsum[NB_NODE];
__device__ int   g_arrive;
__device__ int   g_rowptr[NN + 2];
__device__ int   g_wp[NN];
__device__ __align__(16) EP g_ep[NE];
__device__ __align__(16) float g_TX[4][NN * 32];       // Tx1..Tx4
__device__ __align__(16) float g_h[NN * 32];           // layer-1 output
__device__ __align__(16) float4 g_Wj[2][80 * 96];      // j-major splatted: [j/2][96] of {wj,wj,wj1,wj1}
__device__ float g_bp[2][96];                          // folded biases
__device__ __align__(16) float g_weff[32];             // folded head weight
__device__ float g_beff;

__device__ __forceinline__ const float* sel_ptr(int sel, const float* xext) {
    if (sel == 9) return xext;
    if (sel == 4) return g_h;
    return g_TX[sel];
}

__device__ __forceinline__ float fsig(float x) { return 1.f / (1.f + __expf(-x)); }
__device__ __forceinline__ float ftanh(float x) {
    x = fminf(fmaxf(x, -15.f), 15.f);
    float t = __expf(2.f * x);
    return (t - 1.f) / (t + 1.f);
}

// ---- packed f32x2 helpers (sm_103a FFMA2 is PTX-only) ----
__device__ __forceinline__ ull pk2(float lo, float hi) {
    ull r; asm("mov.b64 %0, {%1, %2};" : "=l"(r) : "f"(lo), "f"(hi)); return r;
}
__device__ __forceinline__ ull ffma2(ull a, ull b, ull c) {
    ull d; asm("fma.rn.f32x2 %0, %1, %2, %3;" : "=l"(d) : "l"(a), "l"(b), "l"(c)); return d;
}
__device__ __forceinline__ void upk2(ull v, float& lo, float& hi) {
    asm("mov.b64 {%0, %1}, %2;" : "=f"(lo), "=f"(hi) : "l"(v));
}

// ---------------- CSR build ----------------
__global__ void k_zero() {
    int i = blockIdx.x * blockDim.x + threadIdx.x;
    if (i < NN) { g_degW[i] = 0.f; g_cnt[i] = 0; }
    if (i == 0) g_arrive = 0;
}

__global__ void k_degree(const int* __restrict__ ei, const float* __restrict__ ew) {
    int q = blockIdx.x * blockDim.x + threadIdx.x;
    if (4 * q >= NE) return;
    int4  s = *(const int4*)(ei + 4 * q);
    int4  d = *(const int4*)(ei + NE + 4 * q);
    float4 w = *(const float4*)(ew + 4 * q);
    atomicAdd(&g_degW[s.x], w.x);
    atomicAdd(&g_degW[s.y], w.y);
    atomicAdd(&g_degW[s.z], w.z);
    atomicAdd(&g_degW[s.w], w.w);
    atomicAdd(&g_cnt[d.x], 1);
    atomicAdd(&g_cnt[d.y], 1);
    atomicAdd(&g_cnt[d.z], 1);
    atomicAdd(&g_cnt[d.w], 1);
}

// dinv + hierarchical scan + rowptr, single kernel (196 blocks all resident -> safe grid barrier)
__global__ void k_mid() {
    __shared__ int sh[256];
    int t = threadIdx.x;
    int b = blockIdx.x;
    int i = b * 256 + t;
    int c = 0;
    if (i < NN) {
        float d = g_degW[i];
        g_dinv[i] = (d > 0.f) ? rsqrtf(fmaxf(d, 1e-12f)) : 0.f;
        c = g_cnt[i];
    }
    sh[t] = c;
    __syncthreads();
    for (int off = 1; off < 256; off <<= 1) {      // inclusive scan (local)
        int v = (t >= off) ? sh[t - off] : 0;
        __syncthreads();
        sh[t] += v;
        __syncthreads();
    }
    int lexcl = sh[t] - c;                          // local exclusive prefix
    if (t == 255) { g_bsum[b] = sh[255]; __threadfence(); }
    __syncthreads();
    if (t == 0) {                                   // grid barrier (all 196 blocks resident)
        atomicAdd(&g_arrive, 1);
        while (atomicAdd(&g_arrive, 0) < (int)gridDim.x) {}
    }
    __syncthreads();
    __threadfence();
    // every block redundantly scans the 196 block sums
    sh[t] = (t < NB_NODE) ? g_bsum[t] : 0;
    __syncthreads();
    for (int off = 1; off < 256; off <<= 1) {
        int v = (t >= off) ? sh[t - off] : 0;
        __syncthreads();
        sh[t] += v;
        __syncthreads();
    }
    int boff = (b == 0) ? 0 : sh[b - 1];
    int total = sh[NB_NODE - 1];
    if (i < NN) {
        int rp = boff + lexcl;
        g_rowptr[i] = rp;
        g_wp[i] = rp;
    }
    if (i == NN) { g_rowptr[NN] = total; g_rowptr[NN + 1] = total; }
}

__global__ void k_scatter(const int* __restrict__ ei, const float* __restrict__ ew) {
    int q = blockIdx.x * blockDim.x + threadIdx.x;
    if (4 * q >= NE) return;
    int4  s = *(const int4*)(ei + 4 * q);
    int4  d = *(const int4*)(ei + NE + 4 * q);
    float4 w = *(const float4*)(ew + 4 * q);
    float ds0 = g_dinv[s.x], ds1 = g_dinv[s.y], ds2 = g_dinv[s.z], ds3 = g_dinv[s.w];
    float dd0 = g_dinv[d.x], dd1 = g_dinv[d.y], dd2 = g_dinv[d.z], dd3 = g_dinv[d.w];
    int p0 = atomicAdd(&g_wp[d.x], 1);
    int p1 = atomicAdd(&g_wp[d.y], 1);
    int p2 = atomicAdd(&g_wp[d.z], 1);
    int p3 = atomicAdd(&g_wp[d.w], 1);
    EP e0; e0.s = s.x; e0.w = -ds0 * w.x * dd0; g_ep[p0] = e0;
    EP e1; e1.s = s.y; e1.w = -ds1 * w.y * dd1; g_ep[p1] = e1;
    EP e2; e2.s = s.z; e2.w = -ds2 * w.z * dd2; g_ep[p2] = e2;
    EP e3; e3.s = s.w; e3.w = -ds3 * w.w * dd3; g_ep[p3] = e3;
}

// ---------------- weight prep (both layers) + head fold, one launch ----------------
__global__ void k_prepw(const float* __restrict__ Wx0, const float* __restrict__ bx0,
                        const float* __restrict__ bh0, const float* __restrict__ bb0,
                        const float* __restrict__ Wx1, const float* __restrict__ bx1,
                        const float* __restrict__ bh1, const float* __restrict__ bb1,
                        const float* __restrict__ hw1, const float* __restrict__ hb1,
                        const float* __restrict__ hw2, const float* __restrict__ hb2,
                        const float* __restrict__ hw3, const float* __restrict__ hb3,
                        const float* __restrict__ hw4, const float* __restrict__ hb4) {
    if (blockIdx.x == 30) {                         // head-fold block (y==0 only)
        if (blockIdx.y != 0 || threadIdx.x >= 32) return;
        int r = threadIdx.x;
        float t1r[16], t2r[8], t3r[4];
        for (int c = 0; c < 16; c++) t1r[c] = hw1[r * 16 + c];
        for (int c = 0; c < 8; c++) {
            float s = 0.f;
            for (int i = 0; i < 16; i++) s += t1r[i] * hw2[i * 8 + c];
            t2r[c] = s;
        }
        for (int c = 0; c < 4; c++) {
            float s = 0.f;
            for (int i = 0; i < 8; i++) s += t2r[i] * hw3[i * 4 + c];
            t3r[c] = s;
        }
        float we = 0.f;
        for (int i = 0; i < 4; i++) we += t3r[i] * hw4[i];
        g_weff[r] = we;
        if (r == 0) {
            float v2[8], v3[4];
            for (int c = 0; c < 8; c++) {
                float s = hb2[c];
                for (int i = 0; i < 16; i++) s += hb1[i] * hw2[i * 8 + c];
                v2[c] = s;
            }
            for (int c = 0; c < 4; c++) {
                float s = hb3[c];
                for (int i = 0; i < 8; i++) s += v2[i] * hw3[i * 4 + c];
                v3[c] = s;
            }
            float b = hb4[0];
            for (int i = 0; i < 4; i++) b += v3[i] * hw4[i];
            g_beff = b;
        }
        return;
    }
    int idx = blockIdx.x * blockDim.x + threadIdx.x;
    if (idx >= 80 * 96) return;
    int layer = blockIdx.y;
    const float* Wx = layer ? Wx1 : Wx0;
    const float* bx = layer ? bx1 : bx0;
    const float* bh = layer ? bh1 : bh0;
    const float* bb = layer ? bb1 : bb0;
    int j2 = idx / 96, o = idx % 96;
    int gi = o >> 5, f = o & 31;
    int g = (gi == 0) ? 0 : ((gi == 1) ? 2 : 3);   // gates i, c, o (forget dead: C=0)
    float w[2];
#pragma unroll
    for (int u = 0; u < 2; u++) {
        int j = 2 * j2 + u;
        int k = j >> 5, jj = j & 31;
        w[u] = Wx[(((g * 5 + k) * 32) + jj) * 32 + f];
    }
    g_Wj[layer][idx] = make_float4(w[0], w[0], w[1], w[1]);
    if (j2 == 0) g_bp[layer][o] = bx[g * 32 + f] + bh[g * 32 + f] + bb[g * 32 + f];
}

// ---------------- sparse propagation: 2 rows/warp, 4 edge-groups x float4, 2 quads/row ----------------
template <bool SUB>
__global__ void k_prop(const float* __restrict__ xext, int insel, int prevsel, int outsel) {
    int wid = (blockIdx.x * blockDim.x + threadIdx.x) >> 5;
    int lane = threadIdx.x & 31;
    int r0 = wid * 2;                // NN even -> every warp owns rows r0, r0+1
    if (r0 >= NN) return;
    const float* xin = sel_ptr(insel, xext);
    int grp = lane >> 3;             // which of 4 edges in the quad
    int fl = (lane & 7) * 4;         // feature slot [fl..fl+3]
    int b0 = g_rowptr[r0];
    int m  = g_rowptr[r0 + 1];       // end of row0 = begin of row1
    int e1v = g_rowptr[r0 + 2];
    float4 a0 = make_float4(0.f, 0.f, 0.f, 0.f);
    float4 a1 = make_float4(0.f, 0.f, 0.f, 0.f);
    int e0 = b0 + grp, e1 = m + grp;
    // joint loop: 2 quads per row per iteration (4 gather lines in flight)
#pragma unroll 1
    for (; e0 + 4 < m && e1 + 4 < e1v; e0 += 8, e1 += 8) {
        EP p00 = g_ep[e0];
        EP p01 = g_ep[e0 + 4];
        EP p10 = g_ep[e1];
        EP p11 = g_ep[e1 + 4];
        const float4 x00 = *(const float4*)(xin + p00.s * 32 + fl);
        const float4 x10 = *(const float4*)(xin + p10.s * 32 + fl);
        const float4 x01 = *(const float4*)(xin + p01.s * 32 + fl);
        const float4 x11 = *(const float4*)(xin + p11.s * 32 + fl);
        a0.x = fmaf(p00.w, x00.x, a0.x); a0.y = fmaf(p00.w, x00.y, a0.y);
        a0.z = fmaf(p00.w, x00.z, a0.z); a0.w = fmaf(p00.w, x00.w, a0.w);
        a1.x = fmaf(p10.w, x10.x, a1.x); a1.y = fmaf(p10.w, x10.y, a1.y);
        a1.z = fmaf(p10.w, x10.z, a1.z); a1.w = fmaf(p10.w, x10.w, a1.w);
        a0.x = fmaf(p01.w, x01.x, a0.x); a0.y = fmaf(p01.w, x01.y, a0.y);
        a0.z = fmaf(p01.w, x01.z, a0.z); a0.w = fmaf(p01.w, x01.w, a0.w);
        a1.x = fmaf(p11.w, x11.x, a1.x); a1.y = fmaf(p11.w, x11.y, a1.y);
        a1.z = fmaf(p11.w, x11.z, a1.z); a1.w = fmaf(p11.w, x11.w, a1.w);
    }
    // drain row0
#pragma unroll 1
    for (; e0 < m; e0 += 4) {
        EP p = g_ep[e0];
        const float4 xv = *(const float4*)(xin + p.s * 32 + fl);
        a0.x = fmaf(p.w, xv.x, a0.x); a0.y = fmaf(p.w, xv.y, a0.y);
        a0.z = fmaf(p.w, xv.z, a0.z); a0.w = fmaf(p.w, xv.w, a0.w);
    }
    // drain row1
#pragma unroll 1
    for (; e1 < e1v; e1 += 4) {
        EP p = g_ep[e1];
        const float4 xv = *(const float4*)(xin + p.s * 32 + fl);
        a1.x = fmaf(p.w, xv.x, a1.x); a1.y = fmaf(p.w, xv.y, a1.y);
        a1.z = fmaf(p.w, xv.z, a1.z); a1.w = fmaf(p.w, xv.w, a1.w);
    }
    // reduce edge-groups for both rows
#pragma unroll
    for (int off = 8; off <= 16; off <<= 1) {
        a0.x += __shfl_xor_sync(0xffffffffu, a0.x, off);
        a0.y += __shfl_xor_sync(0xffffffffu, a0.y, off);
        a0.z += __shfl_xor_sync(0xffffffffu, a0.z, off);
        a0.w += __shfl_xor_sync(0xffffffffu, a0.w, off);
        a1.x += __shfl_xor_sync(0xffffffffu, a1.x, off);
        a1.y += __shfl_xor_sync(0xffffffffu, a1.y, off);
        a1.z += __shfl_xor_sync(0xffffffffu, a1.z, off);
        a1.w += __shfl_xor_sync(0xffffffffu, a1.w, off);
    }
    if (lane < 16) {                 // lanes 0-7 store row0, lanes 8-15 store row1
        int r = (lane < 8) ? r0 : (r0 + 1);
        float4 acc = (lane < 8) ? a0 : a1;
        float* dst = g_TX[outsel] + r * 32 + fl;
        if (SUB) {
            const float* prev = sel_ptr(prevsel, xext) + r * 32 + fl;
            float4 pv = *(const float4*)prev;
            acc.x = 2.f * acc.x - pv.x;
            acc.y = 2.f * acc.y - pv.y;
            acc.z = 2.f * acc.z - pv.z;
            acc.w = 2.f * acc.w - pv.w;
        }
        *(float4*)dst = acc;
    }
}

// ---------------- fused Chebyshev GEMM + gates (+ head), 16 nodes/warp ----------------
// MODE 0: write relu(h) to g_h.   MODE 1: fold head, write out[n].
template <int MODE>
__global__ void __launch_bounds__(128) k_gemm(const float* __restrict__ xext, int insel,
                                              int layer, const float* __restrict__ wc,
                                              float* __restrict__ out) {
    int w = threadIdx.x >> 5, lane = threadIdx.x & 31;
    int n0 = (blockIdx.x * 4 + w) * 16;
    if (n0 >= NN) return;
    const float* planes[5] = {sel_ptr(insel, xext), g_TX[0], g_TX[1], g_TX[2], g_TX[3]};
    const float4* Wj = g_Wj[layer];
    const float* bp = g_bp[layer];
    float b0 = bp[lane], b1 = bp[lane + 32], b2 = bp[lane + 64];
    ull acc[8][3];                               // 8 node-pairs x 3 gate-outputs
#pragma unroll
    for (int p = 0; p < 8; p++) {
        acc[p][0] = pk2(b0, b0);
        acc[p][1] = pk2(b1, b1);
        acc[p][2] = pk2(b2, b2);
    }
#pragma unroll
    for (int k = 0; k < 5; k++) {
        const float* pl = planes[k];
#pragma unroll
        for (int jj = 0; jj < 32; jj += 4) {
            int j2 = (k * 32 + jj) >> 1;
            const float4* Wp = Wj + j2 * 96 + lane;
            ulonglong2 wA0 = *(const ulonglong2*)(Wp);
            ulonglong2 wB0 = *(const ulonglong2*)(Wp + 96);
            ulonglong2 wA1 = *(const ulonglong2*)(Wp + 32);
            ulonglong2 wB1 = *(const ulonglong2*)(Wp + 96 + 32);
            ulonglong2 wA2 = *(const ulonglong2*)(Wp + 64);
            ulonglong2 wB2 = *(const ulonglong2*)(Wp + 96 + 64);
            ull w0[4] = {wA0.x, wA0.y, wB0.x, wB0.y};
            ull w1[4] = {wA1.x, wA1.y, wB1.x, wB1.y};
            ull w2[4] = {wA2.x, wA2.y, wB2.x, wB2.y};
#pragma unroll
            for (int p = 0; p < 8; p++) {
                const float4 xa = *(const float4*)(pl + (n0 + 2 * p) * 32 + jj);
                const float4 xb = *(const float4*)(pl + (n0 + 2 * p + 1) * 32 + jj);
                ull q0 = pk2(xa.x, xb.x);
                ull q1 = pk2(xa.y, xb.y);
                ull q2 = pk2(xa.z, xb.z);
                ull q3 = pk2(xa.w, xb.w);
                acc[p][0] = ffma2(q0, w0[0], acc[p][0]);
                acc[p][1] = ffma2(q0, w1[0], acc[p][1]);
                acc[p][2] = ffma2(q0, w2[0], acc[p][2]);
                acc[p][0] = ffma2(q1, w0[1], acc[p][0]);
                acc[p][1] = ffma2(q1, w1[1], acc[p][1]);
                acc[p][2] = ffma2(q1, w2[1], acc[p][2]);
                acc[p][0] = ffma2(q2, w0[2], acc[p][0]);
                acc[p][1] = ffma2(q2, w1[2], acc[p][1]);
                acc[p][2] = ffma2(q2, w2[2], acc[p][2]);
                acc[p][0] = ffma2(q3, w0[3], acc[p][0]);
                acc[p][1] = ffma2(q3, w1[3], acc[p][1]);
                acc[p][2] = ffma2(q3, w2[3], acc[p][2]);
            }
        }
    }
    // ---- epilogue: gates (i, c, o), H=C=0 GConvLSTM ----
    float wc2 = wc[64 + lane];
    float we = 0.f, be = 0.f;
    if (MODE == 1) { we = g_weff[lane]; be = g_beff; }
#pragma unroll
    for (int p = 0; p < 8; p++) {
        float iv[2], cv[2], ov[2];
        upk2(acc[p][0], iv[0], iv[1]);
        upk2(acc[p][1], cv[0], cv[1]);
        upk2(acc[p][2], ov[0], ov[1]);
#pragma unroll
        for (int u = 0; u < 2; u++) {
            int n = n0 + 2 * p + u;
            float I  = fsig(iv[u]);
            float Cn = I * ftanh(cv[u]);
            float O  = fsig(ov[u] + wc2 * Cn);
            float h  = fmaxf(O * ftanh(Cn), 0.f);
            if (MODE == 0) {
                g_h[n * 32 + lane] = h;
            } else {
                float v = h * we;
#pragma unroll
                for (int off = 16; off > 0; off >>= 1)
                    v += __shfl_xor_sync(0xffffffffu, v, off);
                if (lane == 0) out[n] = v + be;
            }
        }
    }
}

// ---------------- launch ----------------
extern "C" void kernel_launch(void* const* d_in, const int* in_sizes, int n_in,
                              void* d_out, int out_size) {
    const float* x     = (const float*)d_in[0];
    const int*   ei    = (const int*)d_in[1];
    const float* ew    = (const float*)d_in[2];
    const float* l1_Wx = (const float*)d_in[3];
    const float* l1_bx = (const float*)d_in[4];
    const float* l1_bh = (const float*)d_in[6];
    const float* l1_wc = (const float*)d_in[7];
    const float* l1_b  = (const float*)d_in[8];
    const float* l2_Wx = (const float*)d_in[9];
    const float* l2_bx = (const float*)d_in[10];
    const float* l2_bh = (const float*)d_in[12];
    const float* l2_wc = (const float*)d_in[13];
    const float* l2_b  = (const float*)d_in[14];
    const float* hw1   = (const float*)d_in[15];
    const float* hb1   = (const float*)d_in[16];
    const float* hw2   = (const float*)d_in[17];
    const float* hb2   = (const float*)d_in[18];
    const float* hw3   = (const float*)d_in[19];
    const float* hb3   = (const float*)d_in[20];
    const float* hw4   = (const float*)d_in[21];
    const float* hb4   = (const float*)d_in[22];
    float* out = (float*)d_out;

    const int NB_E4 = (NE / 4 + 255) / 256;  // 1563 (4 edges/thread)
    const int NB_W = (NN / 2 * 32 + 255) / 256;  // 3125 (2 rows/warp, 8 warps/block)
    const int NB_G = (NN + 63) / 64;         // 782 (16 nodes/warp, 4 warps/block)

    // graph normalization + CSR
    k_zero<<<NB_NODE, 256>>>();
    k_degree<<<NB_E4, 256>>>(ei, ew);
    k_mid<<<NB_NODE, 256>>>();
    k_scatter<<<NB_E4, 256>>>(ei, ew);

    // weight packing (both layers) + head folding, one launch
    dim3 gp(31, 2);
    k_prepw<<<gp, 256>>>(l1_Wx, l1_bx, l1_bh, l1_b, l2_Wx, l2_bx, l2_bh, l2_b,
                         hw1, hb1, hw2, hb2, hw3, hb3, hw4, hb4);

    // layer 1 (input = x, sel 9) -> g_h
    k_prop<false><<<NB_W, 256>>>(x, 9, -1, 0);
    k_prop<true ><<<NB_W, 256>>>(x, 0, 9, 1);
    k_prop<true ><<<NB_W, 256>>>(x, 1, 0, 2);
    k_prop<true ><<<NB_W, 256>>>(x, 2, 1, 3);
    k_gemm<0><<<NB_G, 128>>>(x, 9, 0, l1_wc, out);

    // layer 2 (input = g_h, sel 4) -> out (head fused)
    k_prop<false><<<NB_W, 256>>>(x, 4, -1, 0);
    k_prop<true ><<<NB_W, 256>>>(x, 0, 4, 1);
    k_prop<true ><<<NB_W, 256>>>(x, 1, 0, 2);
    k_prop<true ><<<NB_W, 256>>>(x, 2, 1, 3);
    k_gemm<1><<<NB_G, 128>>>(x, 4, 1, l2_wc, out);
}

// round 9
// speedup vs baseline: 1.0524x; 1.0524x over previous
#include <cuda_runtime.h>

#define NN 50000
#define NE 1600000
#define NB_NODE 196              // ceil(NN/256)

typedef unsigned long long ull;

struct __align__(8) EP { int s; float w; };

// ---------------- scratch (device globals; no allocations) ----------------
__device__ float g_degW[NN];
__device__ float g_dinv[NN];
__device__ int   g_cnt[NN];
__device__ int   g_bsum[NB_NODE];
__device__ int   g_arrive;
__device__ int   g_rowptr[NN + 2];
__device__ int   g_wp[NN];
__device__ __align__(16) EP g_ep[NE];
__device__ __align__(16) float g_TX[4][NN * 32];       // Tx1..Tx4
__device__ __align__(16) float g_h[NN * 32];           // layer-1 output
__device__ __align__(16) float4 g_Wj[2][80 * 96];      // j-major splatted: [j/2][96] of {wj,wj,wj1,wj1}
__device__ float g_bp[2][96];                          // folded biases
__device__ __align__(16) float g_weff[32];             // folded head weight
__device__ float g_beff;

__device__ __forceinline__ const float* sel_ptr(int sel, const float* xext) {
    if (sel == 9) return xext;
    if (sel == 4) return g_h;
    return g_TX[sel];
}

__device__ __forceinline__ float fsig(float x) { return 1.f / (1.f + __expf(-x)); }
__device__ __forceinline__ float ftanh(float x) {
    x = fminf(fmaxf(x, -15.f), 15.f);
    float t = __expf(2.f * x);
    return (t - 1.f) / (t + 1.f);
}

// ---- packed f32x2 helpers (sm_103a FFMA2 is PTX-only) ----
__device__ __forceinline__ ull pk2(float lo, float hi) {
    ull r; asm("mov.b64 %0, {%1, %2};" : "=l"(r) : "f"(lo), "f"(hi)); return r;
}
__device__ __forceinline__ ull ffma2(ull a, ull b, ull c) {
    ull d; asm("fma.rn.f32x2 %0, %1, %2, %3;" : "=l"(d) : "l"(a), "l"(b), "l"(c)); return d;
}
__device__ __forceinline__ void upk2(ull v, float& lo, float& hi) {
    asm("mov.b64 {%0, %1}, %2;" : "=f"(lo), "=f"(hi) : "l"(v));
}

// ---------------- CSR build ----------------
__global__ void k_zero() {
    int i = blockIdx.x * blockDim.x + threadIdx.x;
    if (i < NN) { g_degW[i] = 0.f; g_cnt[i] = 0; }
    if (i == 0) g_arrive = 0;
}

__global__ void k_degree(const int* __restrict__ ei, const float* __restrict__ ew) {
    int e2 = blockIdx.x * blockDim.x + threadIdx.x;
    if (2 * e2 >= NE) return;
    int2  s = *(const int2*)(ei + 2 * e2);
    int2  d = *(const int2*)(ei + NE + 2 * e2);
    float2 w = *(const float2*)(ew + 2 * e2);
    atomicAdd(&g_degW[s.x], w.x);
    atomicAdd(&g_degW[s.y], w.y);
    atomicAdd(&g_cnt[d.x], 1);
    atomicAdd(&g_cnt[d.y], 1);
}

// dinv + hierarchical scan + rowptr, single kernel (196 blocks all resident -> safe grid barrier)
__global__ void k_mid() {
    __shared__ int sh[256];
    int t = threadIdx.x;
    int b = blockIdx.x;
    int i = b * 256 + t;
    int c = 0;
    if (i < NN) {
        float d = g_degW[i];
        g_dinv[i] = (d > 0.f) ? rsqrtf(fmaxf(d, 1e-12f)) : 0.f;
        c = g_cnt[i];
    }
    sh[t] = c;
    __syncthreads();
    for (int off = 1; off < 256; off <<= 1) {      // inclusive scan (local)
        int v = (t >= off) ? sh[t - off] : 0;
        __syncthreads();
        sh[t] += v;
        __syncthreads();
    }
    int lexcl = sh[t] - c;                          // local exclusive prefix
    if (t == 255) { g_bsum[b] = sh[255]; __threadfence(); }
    __syncthreads();
    if (t == 0) {                                   // grid barrier (all 196 blocks resident)
        atomicAdd(&g_arrive, 1);
        while (atomicAdd(&g_arrive, 0) < (int)gridDim.x) {}
    }
    __syncthreads();
    __threadfence();
    // every block redundantly scans the 196 block sums
    sh[t] = (t < NB_NODE) ? g_bsum[t] : 0;
    __syncthreads();
    for (int off = 1; off < 256; off <<= 1) {
        int v = (t >= off) ? sh[t - off] : 0;
        __syncthreads();
        sh[t] += v;
        __syncthreads();
    }
    int boff = (b == 0) ? 0 : sh[b - 1];
    int total = sh[NB_NODE - 1];
    if (i < NN) {
        int rp = boff + lexcl;
        g_rowptr[i] = rp;
        g_wp[i] = rp;
    }
    if (i == NN) { g_rowptr[NN] = total; g_rowptr[NN + 1] = total; }
}

__global__ void k_scatter(const int* __restrict__ ei, const float* __restrict__ ew) {
    int e2 = blockIdx.x * blockDim.x + threadIdx.x;
    if (2 * e2 >= NE) return;
    int2  s = *(const int2*)(ei + 2 * e2);
    int2  d = *(const int2*)(ei + NE + 2 * e2);
    float2 w = *(const float2*)(ew + 2 * e2);
    int pos0 = atomicAdd(&g_wp[d.x], 1);
    EP p0; p0.s = s.x; p0.w = -g_dinv[s.x] * w.x * g_dinv[d.x];
    g_ep[pos0] = p0;
    int pos1 = atomicAdd(&g_wp[d.y], 1);
    EP p1; p1.s = s.y; p1.w = -g_dinv[s.y] * w.y * g_dinv[d.y];
    g_ep[pos1] = p1;
}

// ---------------- weight prep (both layers) + head fold, one launch ----------------
__global__ void k_prepw(const float* __restrict__ Wx0, const float* __restrict__ bx0,
                        const float* __restrict__ bh0, const float* __restrict__ bb0,
                        const float* __restrict__ Wx1, const float* __restrict__ bx1,
                        const float* __restrict__ bh1, const float* __restrict__ bb1,
                        const float* __restrict__ hw1, const float* __restrict__ hb1,
                        const float* __restrict__ hw2, const float* __restrict__ hb2,
                        const float* __restrict__ hw3, const float* __restrict__ hb3,
                        const float* __restrict__ hw4, const float* __restrict__ hb4) {
    if (blockIdx.x == 30) {                         // head-fold block (y==0 only)
        if (blockIdx.y != 0 || threadIdx.x >= 32) return;
        int r = threadIdx.x;
        float t1r[16], t2r[8], t3r[4];
        for (int c = 0; c < 16; c++) t1r[c] = hw1[r * 16 + c];
        for (int c = 0; c < 8; c++) {
            float s = 0.f;
            for (int i = 0; i < 16; i++) s += t1r[i] * hw2[i * 8 + c];
            t2r[c] = s;
        }
        for (int c = 0; c < 4; c++) {
            float s = 0.f;
            for (int i = 0; i < 8; i++) s += t2r[i] * hw3[i * 4 + c];
            t3r[c] = s;
        }
        float we = 0.f;
        for (int i = 0; i < 4; i++) we += t3r[i] * hw4[i];
        g_weff[r] = we;
        if (r == 0) {
            float v2[8], v3[4];
            for (int c = 0; c < 8; c++) {
                float s = hb2[c];
                for (int i = 0; i < 16; i++) s += hb1[i] * hw2[i * 8 + c];
                v2[c] = s;
            }
            for (int c = 0; c < 4; c++) {
                float s = hb3[c];
                for (int i = 0; i < 8; i++) s += v2[i] * hw3[i * 4 + c];
                v3[c] = s;
            }
            float b = hb4[0];
            for (int i = 0; i < 4; i++) b += v3[i] * hw4[i];
            g_beff = b;
        }
        return;
    }
    int idx = blockIdx.x * blockDim.x + threadIdx.x;
    if (idx >= 80 * 96) return;
    int layer = blockIdx.y;
    const float* Wx = layer ? Wx1 : Wx0;
    const float* bx = layer ? bx1 : bx0;
    const float* bh = layer ? bh1 : bh0;
    const float* bb = layer ? bb1 : bb0;
    int j2 = idx / 96, o = idx % 96;
    int gi = o >> 5, f = o & 31;
    int g = (gi == 0) ? 0 : ((gi == 1) ? 2 : 3);   // gates i, c, o (forget dead: C=0)
    float w[2];
#pragma unroll
    for (int u = 0; u < 2; u++) {
        int j = 2 * j2 + u;
        int k = j >> 5, jj = j & 31;
        w[u] = Wx[(((g * 5 + k) * 32) + jj) * 32 + f];
    }
    g_Wj[layer][idx] = make_float4(w[0], w[0], w[1], w[1]);
    if (j2 == 0) g_bp[layer][o] = bx[g * 32 + f] + bh[g * 32 + f] + bb[g * 32 + f];
}

// ---------------- sparse propagation: 4 edges/warp, EP-prefetch software pipeline ----------------
template <bool SUB>
__global__ void k_prop(const float* __restrict__ xext, int insel, int prevsel, int outsel) {
    int gw = (blockIdx.x * blockDim.x + threadIdx.x) >> 5;
    int lane = threadIdx.x & 31;
    if (gw >= NN) return;
    const float* xin = sel_ptr(insel, xext);
    int grp = lane >> 3;            // which of 4 edges in the quad
    int fl = (lane & 7) * 4;        // feature slot [fl..fl+3]
    int beg = g_rowptr[gw], end = g_rowptr[gw + 1];
    float4 acc = make_float4(0.f, 0.f, 0.f, 0.f);
    int e = beg + grp;
    if (e < end) {
        EP c0 = g_ep[e];
        EP c1 = c0;
        if (e + 4 < end) c1 = g_ep[e + 4];
        // pipelined: prefetch next EP pair before consuming current gathers
#pragma unroll 1
        for (; e + 4 < end; e += 8) {
            EP n0 = c0, n1 = c1;
            if (e + 8 < end)  n0 = g_ep[e + 8];
            if (e + 12 < end) n1 = g_ep[e + 12];
            const float4 xa = *(const float4*)(xin + c0.s * 32 + fl);
            const float4 xb = *(const float4*)(xin + c1.s * 32 + fl);
            acc.x = fmaf(c0.w, xa.x, acc.x);
            acc.y = fmaf(c0.w, xa.y, acc.y);
            acc.z = fmaf(c0.w, xa.z, acc.z);
            acc.w = fmaf(c0.w, xa.w, acc.w);
            acc.x = fmaf(c1.w, xb.x, acc.x);
            acc.y = fmaf(c1.w, xb.y, acc.y);
            acc.z = fmaf(c1.w, xb.z, acc.z);
            acc.w = fmaf(c1.w, xb.w, acc.w);
            c0 = n0; c1 = n1;
        }
        if (e < end) {              // final single quad (c0 already prefetched)
            const float4 xv = *(const float4*)(xin + c0.s * 32 + fl);
            acc.x = fmaf(c0.w, xv.x, acc.x);
            acc.y = fmaf(c0.w, xv.y, acc.y);
            acc.z = fmaf(c0.w, xv.z, acc.z);
            acc.w = fmaf(c0.w, xv.w, acc.w);
        }
    }
    // reduce the 4 edge-groups
#pragma unroll
    for (int off = 8; off <= 16; off <<= 1) {
        acc.x += __shfl_xor_sync(0xffffffffu, acc.x, off);
        acc.y += __shfl_xor_sync(0xffffffffu, acc.y, off);
        acc.z += __shfl_xor_sync(0xffffffffu, acc.z, off);
        acc.w += __shfl_xor_sync(0xffffffffu, acc.w, off);
    }
    if (lane < 8) {
        float* dst = g_TX[outsel] + gw * 32 + fl;
        if (SUB) {
            const float* prev = sel_ptr(prevsel, xext) + gw * 32 + fl;
            float4 pv = *(const float4*)prev;
            acc.x = 2.f * acc.x - pv.x;
            acc.y = 2.f * acc.y - pv.y;
            acc.z = 2.f * acc.z - pv.z;
            acc.w = 2.f * acc.w - pv.w;
        }
        *(float4*)dst = acc;
    }
}

// ---------------- fused Chebyshev GEMM + gates (+ head), 16 nodes/warp ----------------
// MODE 0: write relu(h) to g_h.   MODE 1: fold head, write out[n].
template <int MODE>
__global__ void __launch_bounds__(128) k_gemm(const float* __restrict__ xext, int insel,
                                              int layer, const float* __restrict__ wc,
                                              float* __restrict__ out) {
    int w = threadIdx.x >> 5, lane = threadIdx.x & 31;
    int n0 = (blockIdx.x * 4 + w) * 16;
    if (n0 >= NN) return;
    const float* planes[5] = {sel_ptr(insel, xext), g_TX[0], g_TX[1], g_TX[2], g_TX[3]};
    const float4* Wj = g_Wj[layer];
    const float* bp = g_bp[layer];
    float b0 = bp[lane], b1 = bp[lane + 32], b2 = bp[lane + 64];
    ull acc[8][3];                               // 8 node-pairs x 3 gate-outputs
#pragma unroll
    for (int p = 0; p < 8; p++) {
        acc[p][0] = pk2(b0, b0);
        acc[p][1] = pk2(b1, b1);
        acc[p][2] = pk2(b2, b2);
    }
#pragma unroll
    for (int k = 0; k < 5; k++) {
        const float* pl = planes[k];
#pragma unroll
        for (int jj = 0; jj < 32; jj += 4) {
            int j2 = (k * 32 + jj) >> 1;
            const float4* Wp = Wj + j2 * 96 + lane;
            ulonglong2 wA0 = *(const ulonglong2*)(Wp);
            ulonglong2 wB0 = *(const ulonglong2*)(Wp + 96);
            ulonglong2 wA1 = *(const ulonglong2*)(Wp + 32);
            ulonglong2 wB1 = *(const ulonglong2*)(Wp + 96 + 32);
            ulonglong2 wA2 = *(const ulonglong2*)(Wp + 64);
            ulonglong2 wB2 = *(const ulonglong2*)(Wp + 96 + 64);
            ull w0[4] = {wA0.x, wA0.y, wB0.x, wB0.y};
            ull w1[4] = {wA1.x, wA1.y, wB1.x, wB1.y};
            ull w2[4] = {wA2.x, wA2.y, wB2.x, wB2.y};
#pragma unroll
            for (int p = 0; p < 8; p++) {
                const float4 xa = *(const float4*)(pl + (n0 + 2 * p) * 32 + jj);
                const float4 xb = *(const float4*)(pl + (n0 + 2 * p + 1) * 32 + jj);
                ull q0 = pk2(xa.x, xb.x);
                ull q1 = pk2(xa.y, xb.y);
                ull q2 = pk2(xa.z, xb.z);
                ull q3 = pk2(xa.w, xb.w);
                acc[p][0] = ffma2(q0, w0[0], acc[p][0]);
                acc[p][1] = ffma2(q0, w1[0], acc[p][1]);
                acc[p][2] = ffma2(q0, w2[0], acc[p][2]);
                acc[p][0] = ffma2(q1, w0[1], acc[p][0]);
                acc[p][1] = ffma2(q1, w1[1], acc[p][1]);
                acc[p][2] = ffma2(q1, w2[1], acc[p][2]);
                acc[p][0] = ffma2(q2, w0[2], acc[p][0]);
                acc[p][1] = ffma2(q2, w1[2], acc[p][1]);
                acc[p][2] = ffma2(q2, w2[2], acc[p][2]);
                acc[p][0] = ffma2(q3, w0[3], acc[p][0]);
                acc[p][1] = ffma2(q3, w1[3], acc[p][1]);
                acc[p][2] = ffma2(q3, w2[3], acc[p][2]);
            }
        }
    }
    // ---- epilogue: gates (i, c, o), H=C=0 GConvLSTM ----
    float wc2 = wc[64 + lane];
    float we = 0.f, be = 0.f;
    if (MODE == 1) { we = g_weff[lane]; be = g_beff; }
#pragma unroll
    for (int p = 0; p < 8; p++) {
        float iv[2], cv[2], ov[2];
        upk2(acc[p][0], iv[0], iv[1]);
        upk2(acc[p][1], cv[0], cv[1]);
        upk2(acc[p][2], ov[0], ov[1]);
#pragma unroll
        for (int u = 0; u < 2; u++) {
            int n = n0 + 2 * p + u;
            float I  = fsig(iv[u]);
            float Cn = I * ftanh(cv[u]);
            float O  = fsig(ov[u] + wc2 * Cn);
            float h  = fmaxf(O * ftanh(Cn), 0.f);
            if (MODE == 0) {
                g_h[n * 32 + lane] = h;
            } else {
                float v = h * we;
#pragma unroll
                for (int off = 16; off > 0; off >>= 1)
                    v += __shfl_xor_sync(0xffffffffu, v, off);
                if (lane == 0) out[n] = v + be;
            }
        }
    }
}

// ---------------- launch ----------------
extern "C" void kernel_launch(void* const* d_in, const int* in_sizes, int n_in,
                              void* d_out, int out_size) {
    const float* x     = (const float*)d_in[0];
    const int*   ei    = (const int*)d_in[1];
    const float* ew    = (const float*)d_in[2];
    const float* l1_Wx = (const float*)d_in[3];
    const float* l1_bx = (const float*)d_in[4];
    const float* l1_bh = (const float*)d_in[6];
    const float* l1_wc = (const float*)d_in[7];
    const float* l1_b  = (const float*)d_in[8];
    const float* l2_Wx = (const float*)d_in[9];
    const float* l2_bx = (const float*)d_in[10];
    const float* l2_bh = (const float*)d_in[12];
    const float* l2_wc = (const float*)d_in[13];
    const float* l2_b  = (const float*)d_in[14];
    const float* hw1   = (const float*)d_in[15];
    const float* hb1   = (const float*)d_in[16];
    const float* hw2   = (const float*)d_in[17];
    const float* hb2   = (const float*)d_in[18];
    const float* hw3   = (const float*)d_in[19];
    const float* hb3   = (const float*)d_in[20];
    const float* hw4   = (const float*)d_in[21];
    const float* hb4   = (const float*)d_in[22];
    float* out = (float*)d_out;

    const int NB_E2 = (NE / 2 + 255) / 256;  // 3125 (2 edges/thread)
    const int NB_W = 6250;                   // 50000 warps / 8
    const int NB_G = (NN + 63) / 64;         // 782 (16 nodes/warp, 4 warps/block)

    // graph normalization + CSR
    k_zero<<<NB_NODE, 256>>>();
    k_degree<<<NB_E2, 256>>>(ei, ew);
    k_mid<<<NB_NODE, 256>>>();
    k_scatter<<<NB_E2, 256>>>(ei, ew);

    // weight packing (both layers) + head folding, one launch
    dim3 gp(31, 2);
    k_prepw<<<gp, 256>>>(l1_Wx, l1_bx, l1_bh, l1_b, l2_Wx, l2_bx, l2_bh, l2_b,
                         hw1, hb1, hw2, hb2, hw3, hb3, hw4, hb4);

    // layer 1 (input = x, sel 9) -> g_h
    k_prop<false><<<NB_W, 256>>>(x, 9, -1, 0);
    k_prop<true ><<<NB_W, 256>>>(x, 0, 9, 1);
    k_prop<true ><<<NB_W, 256>>>(x, 1, 0, 2);
    k_prop<true ><<<NB_W, 256>>>(x, 2, 1, 3);
    k_gemm<0><<<NB_G, 128>>>(x, 9, 0, l1_wc, out);

    // layer 2 (input = g_h, sel 4) -> out (head fused)
    k_prop<false><<<NB_W, 256>>>(x, 4, -1, 0);
    k_prop<true ><<<NB_W, 256>>>(x, 0, 4, 1);
    k_prop<true ><<<NB_W, 256>>>(x, 1, 0, 2);
    k_prop<true ><<<NB_W, 256>>>(x, 2, 1, 3);
    k_gemm<1><<<NB_G, 128>>>(x, 4, 1, l2_wc, out);
}

// round 10
// speedup vs baseline: 1.2844x; 1.2204x over previous
#include <cuda_runtime.h>
#include <cuda_fp16.h>

#define NN 50000
#define NE 1600000
#define NB_NODE 196              // ceil(NN/256)

typedef unsigned long long ull;

struct __align__(8) EP { int s; float w; };

// ---------------- scratch (device globals; no allocations) ----------------
__device__ float g_degW[NN];
__device__ float g_dinv[NN];
__device__ int   g_cnt[NN];
__device__ int   g_bsum[NB_NODE];
__device__ int   g_arrive;
__device__ int   g_rowptr[NN + 2];
__device__ int   g_wp[NN];
__device__ __align__(16) EP g_ep[NE];
__device__ __align__(16) __half g_TXh[4][NN * 32];     // Tx1..Tx4 (fp16 storage)
__device__ __align__(16) __half g_hh[NN * 32];         // layer-1 output (fp16)
__device__ __align__(16) float4 g_Wj[2][80 * 96];      // j-major splatted: [j/2][96] of {wj,wj,wj1,wj1}
__device__ float g_bp[2][96];                          // folded biases
__device__ __align__(16) float g_weff[32];             // folded head weight
__device__ float g_beff;

__device__ __forceinline__ const __half* sel_h(int sel) {
    if (sel == 4) return g_hh;
    return g_TXh[sel];
}

__device__ __forceinline__ float fsig(float x) { return 1.f / (1.f + __expf(-x)); }
__device__ __forceinline__ float ftanh(float x) {
    x = fminf(fmaxf(x, -15.f), 15.f);
    float t = __expf(2.f * x);
    return (t - 1.f) / (t + 1.f);
}

// ---- packed f32x2 helpers (sm_103a FFMA2 is PTX-only) ----
__device__ __forceinline__ ull pk2(float lo, float hi) {
    ull r; asm("mov.b64 %0, {%1, %2};" : "=l"(r) : "f"(lo), "f"(hi)); return r;
}
__device__ __forceinline__ ull ffma2(ull a, ull b, ull c) {
    ull d; asm("fma.rn.f32x2 %0, %1, %2, %3;" : "=l"(d) : "l"(a), "l"(b), "l"(c)); return d;
}
__device__ __forceinline__ void upk2(ull v, float& lo, float& hi) {
    asm("mov.b64 {%0, %1}, %2;" : "=f"(lo), "=f"(hi) : "l"(v));
}

// ---------------- CSR build ----------------
__global__ void k_zero() {
    int i = blockIdx.x * blockDim.x + threadIdx.x;
    if (i < NN) { g_degW[i] = 0.f; g_cnt[i] = 0; }
    if (i == 0) g_arrive = 0;
}

__global__ void k_degree(const int* __restrict__ ei, const float* __restrict__ ew) {
    int e2 = blockIdx.x * blockDim.x + threadIdx.x;
    if (2 * e2 >= NE) return;
    int2  s = *(const int2*)(ei + 2 * e2);
    int2  d = *(const int2*)(ei + NE + 2 * e2);
    float2 w = *(const float2*)(ew + 2 * e2);
    atomicAdd(&g_degW[s.x], w.x);
    atomicAdd(&g_degW[s.y], w.y);
    atomicAdd(&g_cnt[d.x], 1);
    atomicAdd(&g_cnt[d.y], 1);
}

// dinv + hierarchical scan + rowptr, single kernel (196 blocks all resident -> safe grid barrier)
__global__ void k_mid() {
    __shared__ int sh[256];
    int t = threadIdx.x;
    int b = blockIdx.x;
    int i = b * 256 + t;
    int c = 0;
    if (i < NN) {
        float d = g_degW[i];
        g_dinv[i] = (d > 0.f) ? rsqrtf(fmaxf(d, 1e-12f)) : 0.f;
        c = g_cnt[i];
    }
    sh[t] = c;
    __syncthreads();
    for (int off = 1; off < 256; off <<= 1) {
        int v = (t >= off) ? sh[t - off] : 0;
        __syncthreads();
        sh[t] += v;
        __syncthreads();
    }
    int lexcl = sh[t] - c;
    if (t == 255) { g_bsum[b] = sh[255]; __threadfence(); }
    __syncthreads();
    if (t == 0) {
        atomicAdd(&g_arrive, 1);
        while (atomicAdd(&g_arrive, 0) < (int)gridDim.x) {}
    }
    __syncthreads();
    __threadfence();
    sh[t] = (t < NB_NODE) ? g_bsum[t] : 0;
    __syncthreads();
    for (int off = 1; off < 256; off <<= 1) {
        int v = (t >= off) ? sh[t - off] : 0;
        __syncthreads();
        sh[t] += v;
        __syncthreads();
    }
    int boff = (b == 0) ? 0 : sh[b - 1];
    int total = sh[NB_NODE - 1];
    if (i < NN) {
        int rp = boff + lexcl;
        g_rowptr[i] = rp;
        g_wp[i] = rp;
    }
    if (i == NN) { g_rowptr[NN] = total; g_rowptr[NN + 1] = total; }
}

__global__ void k_scatter(const int* __restrict__ ei, const float* __restrict__ ew) {
    int e2 = blockIdx.x * blockDim.x + threadIdx.x;
    if (2 * e2 >= NE) return;
    int2  s = *(const int2*)(ei + 2 * e2);
    int2  d = *(const int2*)(ei + NE + 2 * e2);
    float2 w = *(const float2*)(ew + 2 * e2);
    int pos0 = atomicAdd(&g_wp[d.x], 1);
    EP p0; p0.s = s.x; p0.w = -g_dinv[s.x] * w.x * g_dinv[d.x];
    g_ep[pos0] = p0;
    int pos1 = atomicAdd(&g_wp[d.y], 1);
    EP p1; p1.s = s.y; p1.w = -g_dinv[s.y] * w.y * g_dinv[d.y];
    g_ep[pos1] = p1;
}

// ---------------- weight prep (both layers) + head fold, one launch ----------------
__global__ void k_prepw(const float* __restrict__ Wx0, const float* __restrict__ bx0,
                        const float* __restrict__ bh0, const float* __restrict__ bb0,
                        const float* __restrict__ Wx1, const float* __restrict__ bx1,
                        const float* __restrict__ bh1, const float* __restrict__ bb1,
                        const float* __restrict__ hw1, const float* __restrict__ hb1,
                        const float* __restrict__ hw2, const float* __restrict__ hb2,
                        const float* __restrict__ hw3, const float* __restrict__ hb3,
                        const float* __restrict__ hw4, const float* __restrict__ hb4) {
    if (blockIdx.x == 30) {
        if (blockIdx.y != 0 || threadIdx.x >= 32) return;
        int r = threadIdx.x;
        float t1r[16], t2r[8], t3r[4];
        for (int c = 0; c < 16; c++) t1r[c] = hw1[r * 16 + c];
        for (int c = 0; c < 8; c++) {
            float s = 0.f;
            for (int i = 0; i < 16; i++) s += t1r[i] * hw2[i * 8 + c];
            t2r[c] = s;
        }
        for (int c = 0; c < 4; c++) {
            float s = 0.f;
            for (int i = 0; i < 8; i++) s += t2r[i] * hw3[i * 4 + c];
            t3r[c] = s;
        }
        float we = 0.f;
        for (int i = 0; i < 4; i++) we += t3r[i] * hw4[i];
        g_weff[r] = we;
        if (r == 0) {
            float v2[8], v3[4];
            for (int c = 0; c < 8; c++) {
                float s = hb2[c];
                for (int i = 0; i < 16; i++) s += hb1[i] * hw2[i * 8 + c];
                v2[c] = s;
            }
            for (int c = 0; c < 4; c++) {
                float s = hb3[c];
                for (int i = 0; i < 8; i++) s += v2[i] * hw3[i * 4 + c];
                v3[c] = s;
            }
            float b = hb4[0];
            for (int i = 0; i < 4; i++) b += v3[i] * hw4[i];
            g_beff = b;
        }
        return;
    }
    int idx = blockIdx.x * blockDim.x + threadIdx.x;
    if (idx >= 80 * 96) return;
    int layer = blockIdx.y;
    const float* Wx = layer ? Wx1 : Wx0;
    const float* bx = layer ? bx1 : bx0;
    const float* bh = layer ? bh1 : bh0;
    const float* bb = layer ? bb1 : bb0;
    int j2 = idx / 96, o = idx % 96;
    int gi = o >> 5, f = o & 31;
    int g = (gi == 0) ? 0 : ((gi == 1) ? 2 : 3);   // gates i, c, o (forget dead: C=0)
    float w[2];
#pragma unroll
    for (int u = 0; u < 2; u++) {
        int j = 2 * j2 + u;
        int k = j >> 5, jj = j & 31;
        w[u] = Wx[(((g * 5 + k) * 32) + jj) * 32 + f];
    }
    g_Wj[layer][idx] = make_float4(w[0], w[0], w[1], w[1]);
    if (j2 == 0) g_bp[layer][o] = bx[g * 32 + f] + bh[g * 32 + f] + bb[g * 32 + f];
}

// ---------------- sparse propagation ----------------
// INF32: input plane is fp32 (external x). SUBMODE: 0=none, 1=prev fp16 plane, 2=prev fp32 x.
template <bool INF32, int SUBMODE>
__global__ void k_prop(const float* __restrict__ xf, int insel, int prevsel, int outsel) {
    int gw = (blockIdx.x * blockDim.x + threadIdx.x) >> 5;
    int lane = threadIdx.x & 31;
    if (gw >= NN) return;
    const float* xin32 = xf;
    const __half* xin16 = INF32 ? (const __half*)nullptr : sel_h(insel);
    int grp = lane >> 3;            // which of 4 edges in the quad
    int fl = (lane & 7) * 4;        // feature slot [fl..fl+3]
    int beg = g_rowptr[gw], end = g_rowptr[gw + 1];
    float4 acc = make_float4(0.f, 0.f, 0.f, 0.f);
    int e = beg + grp;
    if (e < end) {
        EP c0 = g_ep[e];
        EP c1 = c0;
        if (e + 4 < end) c1 = g_ep[e + 4];
#pragma unroll 1
        for (; e + 4 < end; e += 8) {
            EP n0 = c0, n1 = c1;
            if (e + 8 < end)  n0 = g_ep[e + 8];
            if (e + 12 < end) n1 = g_ep[e + 12];
            float4 xa, xb;
            if (INF32) {
                xa = *(const float4*)(xin32 + c0.s * 32 + fl);
                xb = *(const float4*)(xin32 + c1.s * 32 + fl);
            } else {
                const __half2* pa = (const __half2*)(xin16 + c0.s * 32 + fl);
                const __half2* pb = (const __half2*)(xin16 + c1.s * 32 + fl);
                __half2 a0 = pa[0], a1 = pa[1];
                __half2 b0 = pb[0], b1 = pb[1];
                float2 fa0 = __half22float2(a0), fa1 = __half22float2(a1);
                float2 fb0 = __half22float2(b0), fb1 = __half22float2(b1);
                xa = make_float4(fa0.x, fa0.y, fa1.x, fa1.y);
                xb = make_float4(fb0.x, fb0.y, fb1.x, fb1.y);
            }
            acc.x = fmaf(c0.w, xa.x, acc.x);
            acc.y = fmaf(c0.w, xa.y, acc.y);
            acc.z = fmaf(c0.w, xa.z, acc.z);
            acc.w = fmaf(c0.w, xa.w, acc.w);
            acc.x = fmaf(c1.w, xb.x, acc.x);
            acc.y = fmaf(c1.w, xb.y, acc.y);
            acc.z = fmaf(c1.w, xb.z, acc.z);
            acc.w = fmaf(c1.w, xb.w, acc.w);
            c0 = n0; c1 = n1;
        }
        if (e < end) {
            float4 xv;
            if (INF32) {
                xv = *(const float4*)(xin32 + c0.s * 32 + fl);
            } else {
                const __half2* pa = (const __half2*)(xin16 + c0.s * 32 + fl);
                __half2 a0 = pa[0], a1 = pa[1];
                float2 fa0 = __half22float2(a0), fa1 = __half22float2(a1);
                xv = make_float4(fa0.x, fa0.y, fa1.x, fa1.y);
            }
            acc.x = fmaf(c0.w, xv.x, acc.x);
            acc.y = fmaf(c0.w, xv.y, acc.y);
            acc.z = fmaf(c0.w, xv.z, acc.z);
            acc.w = fmaf(c0.w, xv.w, acc.w);
        }
    }
#pragma unroll
    for (int off = 8; off <= 16; off <<= 1) {
        acc.x += __shfl_xor_sync(0xffffffffu, acc.x, off);
        acc.y += __shfl_xor_sync(0xffffffffu, acc.y, off);
        acc.z += __shfl_xor_sync(0xffffffffu, acc.z, off);
        acc.w += __shfl_xor_sync(0xffffffffu, acc.w, off);
    }
    if (lane < 8) {
        if (SUBMODE == 1) {
            const __half2* pp = (const __half2*)(sel_h(prevsel) + gw * 32 + fl);
            float2 p0 = __half22float2(pp[0]), p1 = __half22float2(pp[1]);
            acc.x = 2.f * acc.x - p0.x;
            acc.y = 2.f * acc.y - p0.y;
            acc.z = 2.f * acc.z - p1.x;
            acc.w = 2.f * acc.w - p1.y;
        } else if (SUBMODE == 2) {
            float4 pv = *(const float4*)(xf + gw * 32 + fl);
            acc.x = 2.f * acc.x - pv.x;
            acc.y = 2.f * acc.y - pv.y;
            acc.z = 2.f * acc.z - pv.z;
            acc.w = 2.f * acc.w - pv.w;
        }
        __half2* dst = (__half2*)(g_TXh[outsel] + gw * 32 + fl);
        dst[0] = __floats2half2_rn(acc.x, acc.y);
        dst[1] = __floats2half2_rn(acc.z, acc.w);
    }
}

// ---------------- fused Chebyshev GEMM + gates (+ head), 16 nodes/warp ----------------
// MODE 0: write relu(h) to g_hh (fp16).  MODE 1: fold head, write out[n] (fp32).
// XF32: plane 0 is external fp32 x (layer 1); otherwise plane 0 is g_hh fp16.
template <int MODE, bool XF32>
__global__ void __launch_bounds__(128) k_gemm(const float* __restrict__ xf, int insel,
                                              int layer, const float* __restrict__ wc,
                                              float* __restrict__ out) {
    int w = threadIdx.x >> 5, lane = threadIdx.x & 31;
    int n0 = (blockIdx.x * 4 + w) * 16;
    if (n0 >= NN) return;
    const __half* planes[5];
    planes[0] = XF32 ? (const __half*)nullptr : sel_h(insel);
    planes[1] = g_TXh[0]; planes[2] = g_TXh[1]; planes[3] = g_TXh[2]; planes[4] = g_TXh[3];
    const float4* Wj = g_Wj[layer];
    const float* bp = g_bp[layer];
    float b0 = bp[lane], b1 = bp[lane + 32], b2 = bp[lane + 64];
    ull acc[8][3];
#pragma unroll
    for (int p = 0; p < 8; p++) {
        acc[p][0] = pk2(b0, b0);
        acc[p][1] = pk2(b1, b1);
        acc[p][2] = pk2(b2, b2);
    }
#pragma unroll
    for (int k = 0; k < 5; k++) {
        const __half* plh = planes[k];
#pragma unroll
        for (int jj = 0; jj < 32; jj += 4) {
            int j2 = (k * 32 + jj) >> 1;
            const float4* Wp = Wj + j2 * 96 + lane;
            ulonglong2 wA0 = *(const ulonglong2*)(Wp);
            ulonglong2 wB0 = *(const ulonglong2*)(Wp + 96);
            ulonglong2 wA1 = *(const ulonglong2*)(Wp + 32);
            ulonglong2 wB1 = *(const ulonglong2*)(Wp + 96 + 32);
            ulonglong2 wA2 = *(const ulonglong2*)(Wp + 64);
            ulonglong2 wB2 = *(const ulonglong2*)(Wp + 96 + 64);
            ull w0[4] = {wA0.x, wA0.y, wB0.x, wB0.y};
            ull w1[4] = {wA1.x, wA1.y, wB1.x, wB1.y};
            ull w2[4] = {wA2.x, wA2.y, wB2.x, wB2.y};
#pragma unroll
            for (int p = 0; p < 8; p++) {
                int na = n0 + 2 * p, nb = na + 1;
                float4 xa, xb;
                if (XF32 && k == 0) {
                    xa = *(const float4*)(xf + na * 32 + jj);
                    xb = *(const float4*)(xf + nb * 32 + jj);
                } else {
                    const __half2* pa = (const __half2*)(plh + na * 32 + jj);
                    const __half2* pb = (const __half2*)(plh + nb * 32 + jj);
                    __half2 a0 = pa[0], a1 = pa[1];
                    __half2 b0h = pb[0], b1h = pb[1];
                    float2 fa0 = __half22float2(a0), fa1 = __half22float2(a1);
                    float2 fb0 = __half22float2(b0h), fb1 = __half22float2(b1h);
                    xa = make_float4(fa0.x, fa0.y, fa1.x, fa1.y);
                    xb = make_float4(fb0.x, fb0.y, fb1.x, fb1.y);
                }
                ull q0 = pk2(xa.x, xb.x);
                ull q1 = pk2(xa.y, xb.y);
                ull q2 = pk2(xa.z, xb.z);
                ull q3 = pk2(xa.w, xb.w);
                acc[p][0] = ffma2(q0, w0[0], acc[p][0]);
                acc[p][1] = ffma2(q0, w1[0], acc[p][1]);
                acc[p][2] = ffma2(q0, w2[0], acc[p][2]);
                acc[p][0] = ffma2(q1, w0[1], acc[p][0]);
                acc[p][1] = ffma2(q1, w1[1], acc[p][1]);
                acc[p][2] = ffma2(q1, w2[1], acc[p][2]);
                acc[p][0] = ffma2(q2, w0[2], acc[p][0]);
                acc[p][1] = ffma2(q2, w1[2], acc[p][1]);
                acc[p][2] = ffma2(q2, w2[2], acc[p][2]);
                acc[p][0] = ffma2(q3, w0[3], acc[p][0]);
                acc[p][1] = ffma2(q3, w1[3], acc[p][1]);
                acc[p][2] = ffma2(q3, w2[3], acc[p][2]);
            }
        }
    }
    // ---- epilogue: gates (i, c, o), H=C=0 GConvLSTM ----
    float wc2 = wc[64 + lane];
    float we = 0.f, be = 0.f;
    if (MODE == 1) { we = g_weff[lane]; be = g_beff; }
#pragma unroll
    for (int p = 0; p < 8; p++) {
        float iv[2], cv[2], ov[2];
        upk2(acc[p][0], iv[0], iv[1]);
        upk2(acc[p][1], cv[0], cv[1]);
        upk2(acc[p][2], ov[0], ov[1]);
#pragma unroll
        for (int u = 0; u < 2; u++) {
            int n = n0 + 2 * p + u;
            float I  = fsig(iv[u]);
            float Cn = I * ftanh(cv[u]);
            float O  = fsig(ov[u] + wc2 * Cn);
            float h  = fmaxf(O * ftanh(Cn), 0.f);
            if (MODE == 0) {
                g_hh[n * 32 + lane] = __float2half_rn(h);
            } else {
                float v = h * we;
#pragma unroll
                for (int off = 16; off > 0; off >>= 1)
                    v += __shfl_xor_sync(0xffffffffu, v, off);
                if (lane == 0) out[n] = v + be;
            }
        }
    }
}

// ---------------- launch ----------------
extern "C" void kernel_launch(void* const* d_in, const int* in_sizes, int n_in,
                              void* d_out, int out_size) {
    const float* x     = (const float*)d_in[0];
    const int*   ei    = (const int*)d_in[1];
    const float* ew    = (const float*)d_in[2];
    const float* l1_Wx = (const float*)d_in[3];
    const float* l1_bx = (const float*)d_in[4];
    const float* l1_bh = (const float*)d_in[6];
    const float* l1_wc = (const float*)d_in[7];
    const float* l1_b  = (const float*)d_in[8];
    const float* l2_Wx = (const float*)d_in[9];
    const float* l2_bx = (const float*)d_in[10];
    const float* l2_bh = (const float*)d_in[12];
    const float* l2_wc = (const float*)d_in[13];
    const float* l2_b  = (const float*)d_in[14];
    const float* hw1   = (const float*)d_in[15];
    const float* hb1   = (const float*)d_in[16];
    const float* hw2   = (const float*)d_in[17];
    const float* hb2   = (const float*)d_in[18];
    const float* hw3   = (const float*)d_in[19];
    const float* hb3   = (const float*)d_in[20];
    const float* hw4   = (const float*)d_in[21];
    const float* hb4   = (const float*)d_in[22];
    float* out = (float*)d_out;

    const int NB_E2 = (NE / 2 + 255) / 256;  // 3125 (2 edges/thread)
    const int NB_W = 6250;                   // 50000 warps / 8
    const int NB_G = (NN + 63) / 64;         // 782 (16 nodes/warp, 4 warps/block)

    // graph normalization + CSR
    k_zero<<<NB_NODE, 256>>>();
    k_degree<<<NB_E2, 256>>>(ei, ew);
    k_mid<<<NB_NODE, 256>>>();
    k_scatter<<<NB_E2, 256>>>(ei, ew);

    // weight packing (both layers) + head folding, one launch
    dim3 gp(31, 2);
    k_prepw<<<gp, 256>>>(l1_Wx, l1_bx, l1_bh, l1_b, l2_Wx, l2_bx, l2_bh, l2_b,
                         hw1, hb1, hw2, hb2, hw3, hb3, hw4, hb4);

    // layer 1 (input = x fp32) -> g_hh (fp16)
    k_prop<true,  0><<<NB_W, 256>>>(x, 9, -1, 0);
    k_prop<false, 2><<<NB_W, 256>>>(x, 0,  9, 1);   // prev = x (fp32)
    k_prop<false, 1><<<NB_W, 256>>>(x, 1,  0, 2);
    k_prop<false, 1><<<NB_W, 256>>>(x, 2,  1, 3);
    k_gemm<0, true><<<NB_G, 128>>>(x, 9, 0, l1_wc, out);

    // layer 2 (input = g_hh fp16) -> out (head fused)
    k_prop<false, 0><<<NB_W, 256>>>(x, 4, -1, 0);
    k_prop<false, 1><<<NB_W, 256>>>(x, 0,  4, 1);
    k_prop<false, 1><<<NB_W, 256>>>(x, 1,  0, 2);
    k_prop<false, 1><<<NB_W, 256>>>(x, 2,  1, 3);
    k_gemm<1, false><<<NB_G, 128>>>(x, 4, 1, l2_wc, out);
}